// round 7
// baseline (speedup 1.0000x reference)
#include <cuda_runtime.h>
#include <cstdint>

#define BB 32
#define TT 512
#define KK 48
#define SROW 56              // tile row stride (words)
#define TILESZ (KK * SROW)   // 2688
#define ERS 52               // Es row stride (words), j-major: Es[j*ERS + i]
#define ESZ (KK * ERS)       // 2496
#define NTH 192              // 6 warps: w0,w1 consumers; w2..w5 producers (1/SMSP)
#define NB 6
#define START_TAG 46
#define STOP_TAG 47

__device__ float g_partials[BB];
__device__ int   g_ctr = 0;

__device__ __forceinline__ float ex2f(float x) {
    float y; asm("ex2.approx.ftz.f32 %0, %1;" : "=f"(y) : "f"(x)); return y;
}
__device__ __forceinline__ float lg2f(float x) {
    float y; asm("lg2.approx.ftz.f32 %0, %1;" : "=f"(y) : "f"(x)); return y;
}
__device__ __forceinline__ void cp16(uint32_t smem, const void* g) {
    asm volatile("cp.async.cg.shared.global [%0], [%1], 16;" :: "r"(smem), "l"(g));
}
__device__ __forceinline__ void cp_commit() { asm volatile("cp.async.commit_group;"); }
__device__ __forceinline__ void cp_wait3()  { asm volatile("cp.async.wait_group 3;"); }
__device__ __forceinline__ void cp_wait4()  { asm volatile("cp.async.wait_group 4;"); }

extern __shared__ float smem_dyn[];

__global__ __launch_bounds__(NTH, 1)
void crf_fwd_kernel(const float* __restrict__ feat,
                    const int*   __restrict__ targets,
                    const int*   __restrict__ lengths,
                    float*       __restrict__ out)
{
    float* tile = smem_dyn;                       // NB * TILESZ
    float* Es   = tile + NB * TILESZ;             // 2 * ESZ  (double-buffered exp tiles)
    float* cbuf = Es + 2 * ESZ;                   // 2 * 64   (raw linear carries)
    int*   tsh  = (int*)(cbuf + 2 * 64);          // TT
    float* goldSh = (float*)(tsh + TT);           // 1

    const int b   = blockIdx.x;
    const int tid = threadIdx.x;
    const int len = lengths[b];
    const float* fb = feat + (size_t)b * TT * (KK * KK);

    for (int i = tid; i < TT; i += NTH) {
        int v = targets[b * TT + i];
        tsh[i] = (v / KK) * SROW + (v % KK);
    }

    const int l = tid & 31;
    const int w = tid >> 5;

    // ---- consumer mapping: w0 -> cols 0..31, w1 -> cols 32..47 (16 lanes) ----
    const bool is_cons = (w < 2);
    const bool cactive = is_cons && (w == 0 || l < 16);
    const int  cj      = (w == 0) ? l : 32 + l;

    // ---- producer mapping: plane in 0..127; element-pairs ep = plane + 128k ----
    // period-3 structure: j(k) has period 3, i-pair advances +8 per period
    const int plane = (w - 2) * 32 + l;
    int toff[3], eoff[3];
    #pragma unroll
    for (int m = 0; m < 3; ++m) {
        int ep = plane + 128 * m;
        int jm = ep % 48;
        int im = ep / 48;                 // i-pair index (i = 2*im)
        toff[m] = 2 * im * SROW + jm;     // tile word offset
        eoff[m] = jm * ERS + 2 * im;      // Es word offset
    }

    // prefetch chunks: 3 per thread (576 = 3*192)
    uint32_t so[3]; size_t go[3];
    #pragma unroll
    for (int q = 0; q < 3; ++q) {
        int k = tid + q * NTH;
        so[q] = (uint32_t)((k / 12) * SROW * 4 + (k % 12) * 16);
        go[q] = (size_t)(k / 12) * KK + (size_t)(k % 12) * 4;
    }
    uint32_t sb[NB];
    #pragma unroll
    for (int n = 0; n < NB; ++n)
        sb[n] = (uint32_t)__cvta_generic_to_shared(tile + n * TILESZ);

    const float LOG2E = 1.4426950408889634f;
    const float LN2   = 0.6931471805599453f;

    // Prologue: issue tiles 0..4 as 5 groups
    #pragma unroll
    for (int tt = 0; tt < 5; ++tt) {
        if (tt < len) {
            const float* src = fb + (size_t)tt * (KK * KK);
            #pragma unroll
            for (int q = 0; q < 3; ++q) cp16(sb[tt] + so[q], src + go[q]);
        }
        cp_commit();
    }
    cp_wait4();
    __syncthreads();                 // tile 0 visible

    // init: raw carries c(0) = 2^(f0[START,:]*log2e)
    if (cactive) cbuf[cj] = ex2f(tile[SROW * START_TAG + cj] * LOG2E);
    float gold = 0.f;
    int   eacc = 0;
    if (tid == 64) gold = tile[tsh[0]];    // gold thread = producer w2 l0

    cp_wait3();
    __syncthreads();                 // tile 1 visible

    // pre-loop producer stage: E(1) -> Es[1]
    if (!is_cons && len > 1) {
        const float* Tb = tile + 1 * TILESZ;
        float* Eb = Es + 1 * ESZ;
        #pragma unroll
        for (int m = 0; m < 3; ++m) {
            #pragma unroll
            for (int q = 0; q < 3; ++q) {
                float f0 = Tb[toff[m] + 896 * q];
                float f1 = Tb[toff[m] + 896 * q + SROW];
                float2 e;
                e.x = ex2f(f0 * LOG2E);
                e.y = ex2f(f1 * LOG2E);
                *(float2*)(Eb + eoff[m] + 16 * q) = e;
            }
        }
        if (tid == 64) gold += Tb[tsh[1]];
    }
    if (5 < len) {
        const float* src = fb + (size_t)5 * (KK * KK);
        #pragma unroll
        for (int q = 0; q < 3; ++q) cp16(sb[5] + so[q], src + go[q]);
    }
    cp_commit();

    int nxt = 2;   // (t+1) % NB
    int pfb = 0;   // (t+5) % NB
    for (int t = 1; t < len; ++t) {
        cp_wait3();
        __syncthreads();   // tile t+1, Es[t&1], cbuf[(t-1)&1] all visible

        // prefetch tile t+5
        {
            int tn = t + 5;
            if (tn < len) {
                const float* src = fb + (size_t)tn * (KK * KK);
                uint32_t dst = sb[pfb];
                #pragma unroll
                for (int q = 0; q < 3; ++q) cp16(dst + so[q], src + go[q]);
            }
            cp_commit();
        }

        if (is_cons) {
            if (cactive) {
                const float* Ej = Es + (t & 1) * ESZ + cj * ERS;
                const float* cr = cbuf + ((t - 1) & 1) * 64;
                float c0 = cr[0];
                uint32_t cbits = __float_as_uint(c0);
                int be = (int)(cbits >> 23);
                float rsc = __uint_as_float((uint32_t)(254 - be) << 23);

                float a0=0.f,a1=0.f,a2=0.f,a3=0.f,a4=0.f,a5=0.f,a6=0.f,a7=0.f;
                #pragma unroll
                for (int k = 0; k < 12; k += 2) {
                    float4 C0 = *(const float4*)(cr + 4 * k);
                    float4 E0 = *(const float4*)(Ej + 4 * k);
                    float4 C1 = *(const float4*)(cr + 4 * k + 4);
                    float4 E1 = *(const float4*)(Ej + 4 * k + 4);
                    a0 = fmaf(E0.x, C0.x, a0);
                    a1 = fmaf(E0.y, C0.y, a1);
                    a2 = fmaf(E0.z, C0.z, a2);
                    a3 = fmaf(E0.w, C0.w, a3);
                    a4 = fmaf(E1.x, C1.x, a4);
                    a5 = fmaf(E1.y, C1.y, a5);
                    a6 = fmaf(E1.z, C1.z, a6);
                    a7 = fmaf(E1.w, C1.w, a7);
                }
                float acc = ((a0 + a1) + (a2 + a3)) + ((a4 + a5) + (a6 + a7));
                cbuf[(t & 1) * 64 + cj] = acc * rsc;
                if (tid == 0) eacc += be - 127;
            }
        } else if (t + 1 < len) {
            // producers: E(t+1) -> Es[(t+1)&1]
            const float* Tb = tile + nxt * TILESZ;
            float* Eb = Es + ((t + 1) & 1) * ESZ;
            #pragma unroll
            for (int m = 0; m < 3; ++m) {
                #pragma unroll
                for (int q = 0; q < 3; ++q) {
                    float f0 = Tb[toff[m] + 896 * q];
                    float f1 = Tb[toff[m] + 896 * q + SROW];
                    float2 e;
                    e.x = ex2f(f0 * LOG2E);
                    e.y = ex2f(f1 * LOG2E);
                    *(float2*)(Eb + eoff[m] + 16 * q) = e;
                }
            }
            if (tid == 64) gold += Tb[tsh[t + 1]];
        }

        if (++nxt == NB) nxt = 0;
        if (++pfb == NB) pfb = 0;
    }

    if (tid == 64) *goldSh = gold;
    __syncthreads();
    if (tid == 0) {
        float fin = ((float)eacc + lg2f(cbuf[((len - 1) & 1) * 64 + STOP_TAG])) * LN2;
        g_partials[b] = fin - *goldSh;
    }

    // fused deterministic batch reduction (last block)
    if (tid < 32) {
        int old = 0;
        if (tid == 0) {
            __threadfence();
            old = atomicAdd(&g_ctr, 1);
        }
        old = __shfl_sync(0xffffffffu, old, 0);
        if (old == BB - 1) {
            __threadfence();
            float v = g_partials[tid];
            #pragma unroll
            for (int o = 16; o; o >>= 1) v += __shfl_down_sync(0xffffffffu, v, o);
            if (tid == 0) { out[0] = v / (float)BB; g_ctr = 0; }
        }
    }
}

extern "C" void kernel_launch(void* const* d_in, const int* in_sizes, int n_in,
                              void* d_out, int out_size)
{
    const float* feat    = (const float*)d_in[0];
    const int*   targets = (const int*)d_in[1];
    const int*   lengths = (const int*)d_in[2];
    float*       out     = (float*)d_out;

    const int smem_bytes = (NB * TILESZ + 2 * ESZ + 2 * 64) * 4 + TT * 4 + 16;
    cudaFuncSetAttribute(crf_fwd_kernel, cudaFuncAttributeMaxDynamicSharedMemorySize, smem_bytes);
    crf_fwd_kernel<<<BB, NTH, smem_bytes>>>(feat, targets, lengths, out);
}

// round 8
// speedup vs baseline: 1.6087x; 1.6087x over previous
#include <cuda_runtime.h>
#include <cstdint>

#define BB 32
#define TT 512
#define KK 48
#define SROW 52              // banks (20u + c) % 32 all distinct for u=0..7, c=0..3
#define TILESZ (KK * SROW)   // 2496
#define NTH 384              // 12 warps -> {3,3,3,3} per SMSP (balanced MUFU + issue)
#define NB 6
#define NCHUNK 576
#define CARRYSZ 96           // slot for tag i: 12*(i&7) + (i>>3)
#define START_TAG 46
#define STOP_TAG 47

__device__ float g_partials[BB];
__device__ int   g_ctr = 0;

__device__ __forceinline__ float ex2f_pin(float x) {
    float y; asm volatile("ex2.approx.ftz.f32 %0, %1;" : "=f"(y) : "f"(x)); return y;
}
__device__ __forceinline__ float ex2f(float x) {
    float y; asm("ex2.approx.ftz.f32 %0, %1;" : "=f"(y) : "f"(x)); return y;
}
__device__ __forceinline__ float lg2f(float x) {
    float y; asm("lg2.approx.ftz.f32 %0, %1;" : "=f"(y) : "f"(x)); return y;
}
__device__ __forceinline__ void cp16(uint32_t smem, const void* g) {
    asm volatile("cp.async.cg.shared.global [%0], [%1], 16;" :: "r"(smem), "l"(g));
}
__device__ __forceinline__ void cp_commit() { asm volatile("cp.async.commit_group;"); }
__device__ __forceinline__ void cp_wait3()  { asm volatile("cp.async.wait_group 3;"); }
__device__ __forceinline__ void cp_wait4()  { asm volatile("cp.async.wait_group 4;"); }

// tag i = u + 8*ii (u=0..7, ii=0..5) -> slot 12u + ii
__device__ __forceinline__ int pslot(int i) { return 12 * (i & 7) + (i >> 3); }

extern __shared__ float smem_dyn[];

__global__ __launch_bounds__(NTH, 1)
void crf_fwd_kernel(const float* __restrict__ feat,
                    const int*   __restrict__ targets,
                    const int*   __restrict__ lengths,
                    float*       __restrict__ out)
{
    float* tile = smem_dyn;                      // NB * TILESZ
    float* cbuf = tile + NB * TILESZ;            // 2 * CARRYSZ
    int*   tsh  = (int*)(cbuf + 2 * CARRYSZ);    // TT

    const int b   = blockIdx.x;
    const int tid = threadIdx.x;
    const int len = lengths[b];
    const float* fb = feat + (size_t)b * TT * (KK * KK);

    for (int i = tid; i < TT; i += NTH) {
        int v = targets[b * TT + i];
        tsh[i] = (v / KK) * SROW + (v % KK);
    }

    // warp w owns columns 4w..4w+3: j = 4w + (l&3); i = u + 8*ii, u = l>>2
    const int l = tid & 31;
    const int w = tid >> 5;
    const int j = 4 * w + (l & 3);
    const int u = l >> 2;

    // prefetch chunks: 576 over 384 threads (first 192 take a second one)
    const int k0 = tid;
    const int k1 = tid + NTH;
    const bool has1 = (k1 < NCHUNK);
    const uint32_t so0 = (uint32_t)((k0 / 12) * SROW * 4 + (k0 % 12) * 16);
    const size_t   go0 = (size_t)(k0 / 12) * KK + (size_t)(k0 % 12) * 4;
    const uint32_t so1 = (uint32_t)((k1 / 12) * SROW * 4 + (k1 % 12) * 16);
    const size_t   go1 = (size_t)(k1 / 12) * KK + (size_t)(k1 % 12) * 4;

    uint32_t sb[NB];
    #pragma unroll
    for (int n = 0; n < NB; ++n)
        sb[n] = (uint32_t)__cvta_generic_to_shared(tile + n * TILESZ);

    const float LOG2E = 1.4426950408889634f;
    const float LN2   = 0.6931471805599453f;

    // Prologue: issue tiles 0..4 as 5 groups
    #pragma unroll
    for (int tt = 0; tt < 5; ++tt) {
        if (tt < len) {
            const float* src = fb + (size_t)tt * (KK * KK);
            cp16(sb[tt] + so0, src + go0);
            if (has1) cp16(sb[tt] + so1, src + go1);
        }
        cp_commit();
    }
    cp_wait4();
    __syncthreads();                 // tile 0 visible

    // init raw linear carries c(0) into buffer 0
    if (tid < KK) cbuf[pslot(tid)] = ex2f(tile[SROW * START_TAG + tid] * LOG2E);
    float gold = 0.f;
    int   eacc = 0;
    if (tid == 0) gold = tile[tsh[0]];

    cp_wait3();
    __syncthreads();                 // tile 1 + init carries visible

    // E for tile 1 (6 per lane, registers)
    float E[6];
    {
        const float* fn = tile + 1 * TILESZ + u * SROW + j;
        #pragma unroll
        for (int ii = 0; ii < 6; ++ii)
            E[ii] = ex2f_pin(fn[8 * SROW * ii] * LOG2E);
    }
    if (5 < len) {
        const float* src = fb + (size_t)5 * (KK * KK);
        cp16(sb[5] + so0, src + go0);
        if (has1) cp16(sb[5] + so1, src + go1);
    }
    cp_commit();

    int cur = 1;   // t % NB
    int nxt = 2;   // (t+1) % NB
    int pfb = 0;   // (t+5) % NB
    for (int t = 1; t < len; ++t) {
        cp_wait3();
        __syncthreads();     // carries(t-1) + tile t+1 visible; buffer pfb drained

        // prefetch tile t+5
        {
            int tn = t + 5;
            if (tn < len) {
                const float* src = fb + (size_t)tn * (KK * KK);
                uint32_t dst = sb[pfb];
                cp16(dst + so0, src + go0);
                if (has1) cp16(dst + so1, src + go1);
            }
            cp_commit();
        }

        const float* dr = cbuf + ((t - 1) & 1) * CARRYSZ;
        const float  c0 = dr[0];
        const uint32_t cbits = __float_as_uint(c0);
        const int      be = (int)(cbits >> 23);
        const float    rsc = __uint_as_float((uint32_t)(254 - be) << 23);

        float4 A  = *(const float4*)(dr + 12 * u);      // carries ii=0..3
        float2 Bc = *(const float2*)(dr + 12 * u + 4);  // carries ii=4..5

        float a0 = E[0] * A.x;
        float a1 = E[1] * A.y;
        a0 = fmaf(E[2], A.z, a0);
        a1 = fmaf(E[3], A.w, a1);
        a0 = fmaf(E[4], Bc.x, a0);
        a1 = fmaf(E[5], Bc.y, a1);
        float acc = a0 + a1;

        if (tid == 0) {
            eacc += be - 127;
            gold += tile[cur * TILESZ + tsh[t]];
        }

        acc += __shfl_xor_sync(0xffffffffu, acc, 4);
        acc += __shfl_xor_sync(0xffffffffu, acc, 8);
        acc += __shfl_xor_sync(0xffffffffu, acc, 16);
        if (u == 0) cbuf[(t & 1) * CARRYSZ + pslot(j)] = acc * rsc;

        // E for tile t+1 (pinned pre-barrier; dead at t = len-1, harmless)
        {
            const float* fn = tile + nxt * TILESZ + u * SROW + j;
            #pragma unroll
            for (int ii = 0; ii < 6; ++ii)
                E[ii] = ex2f_pin(fn[8 * SROW * ii] * LOG2E);
        }

        if (++cur == NB) cur = 0;
        if (++nxt == NB) nxt = 0;
        if (++pfb == NB) pfb = 0;
    }

    __syncthreads();
    if (tid == 0) {
        float fin = ((float)eacc + lg2f(cbuf[((len - 1) & 1) * CARRYSZ + pslot(STOP_TAG)])) * LN2;
        g_partials[b] = fin - gold;
    }

    // fused deterministic batch reduction (last block)
    if (tid < 32) {
        int old = 0;
        if (tid == 0) {
            __threadfence();
            old = atomicAdd(&g_ctr, 1);
        }
        old = __shfl_sync(0xffffffffu, old, 0);
        if (old == BB - 1) {
            __threadfence();
            float v = g_partials[tid];
            #pragma unroll
            for (int o = 16; o; o >>= 1) v += __shfl_down_sync(0xffffffffu, v, o);
            if (tid == 0) { out[0] = v / (float)BB; g_ctr = 0; }
        }
    }
}

extern "C" void kernel_launch(void* const* d_in, const int* in_sizes, int n_in,
                              void* d_out, int out_size)
{
    const float* feat    = (const float*)d_in[0];
    const int*   targets = (const int*)d_in[1];
    const int*   lengths = (const int*)d_in[2];
    float*       out     = (float*)d_out;

    const int smem_bytes = (NB * TILESZ + 2 * CARRYSZ) * 4 + TT * 4;  // ~62.4 KB
    cudaFuncSetAttribute(crf_fwd_kernel, cudaFuncAttributeMaxDynamicSharedMemorySize, smem_bytes);
    crf_fwd_kernel<<<BB, NTH, smem_bytes>>>(feat, targets, lengths, out);
}